// round 16
// baseline (speedup 1.0000x reference)
#include <cuda_runtime.h>
#include <cuda_fp16.h>
#include <cstdint>

#define BATCH 32
#define C_IN 128
#define C_OUT 256
#define HGT 56
#define WID 56
#define HW 3136
#define BN_EPS 1e-5f
#define DW_THRESH 4.0f
#define PW_THRESH 0.001f

#define NTILES 25               // ceil(3136/128) pixel tiles
#define MC 128                  // co per CTA tile
#define NC 128                  // pixels per CTA tile
#define SSTR 136                // smem row stride in halfs (128 + 8 pad)
#define AS_HALFS (MC * SSTR)    // 17408 halfs = 34816 B
#define NUNITS 1600             // 2 co-blocks * 32 batch * 25 tiles
#define NPW 296                 // persistent CTAs (2 per SM * 148)
#define PW_SMEM_BYTES (3 * AS_HALFS * 2 + 256)   // A + 2xB

#define XPAD_TOP 56             // dw smem top pad (zeroed)
#define XPAD_BOT 57             // dw smem bottom pad (zeroed)

// ---------------- device scratch ----------------
__device__ __half g_y[BATCH * C_IN * HW];       // post-dw activations [b][ci][pix]
__device__ __half g_w2[C_OUT * C_IN];           // BN2-folded weights [co][ci]
__device__ float g_bias2[C_OUT];
__device__ unsigned int g_max[BATCH * C_OUT];
__device__ unsigned char g_keep[BATCH * C_IN];  // cut-1 survival flag
__device__ int g_unit;                          // pw work-steal ticket counter

__device__ __forceinline__ void ldsm_x4(uint32_t* r, uint32_t addr) {
    asm volatile("ldmatrix.sync.aligned.m8n8.x4.shared.b16 {%0,%1,%2,%3}, [%4];"
                 : "=r"(r[0]), "=r"(r[1]), "=r"(r[2]), "=r"(r[3]) : "r"(addr));
}
__device__ __forceinline__ void ldsm_x4_t(uint32_t* r, uint32_t addr) {
    asm volatile("ldmatrix.sync.aligned.m8n8.x4.trans.shared.b16 {%0,%1,%2,%3}, [%4];"
                 : "=r"(r[0]), "=r"(r[1]), "=r"(r[2]), "=r"(r[3]) : "r"(addr));
}
__device__ __forceinline__ void mma_f16(float* c, const uint32_t* a, const uint32_t* b) {
    asm volatile(
        "mma.sync.aligned.m16n8k16.row.col.f32.f16.f16.f32 "
        "{%0,%1,%2,%3}, {%4,%5,%6,%7}, {%8,%9}, {%0,%1,%2,%3};"
        : "+f"(c[0]), "+f"(c[1]), "+f"(c[2]), "+f"(c[3])
        : "r"(a[0]), "r"(a[1]), "r"(a[2]), "r"(a[3]), "r"(b[0]), "r"(b[1]));
}
__device__ __forceinline__ void cp_async16(uint32_t dst, const void* src, int src_size) {
    asm volatile("cp.async.cg.shared.global [%0], [%1], 16, %2;"
                 :: "r"(dst), "l"(src), "r"(src_size) : "memory");
}
__device__ __forceinline__ void cp_async_commit() {
    asm volatile("cp.async.commit_group;" ::: "memory");
}
template <int N>
__device__ __forceinline__ void cp_async_wait() {
    asm volatile("cp.async.wait_group %0;" :: "n"(N) : "memory");
}

// ---------------------------------------------------------------------------
// K1: depthwise 3x3 + bias + BN1 + ReLU + cut(4.0)  (R11 version, measured)
// ---------------------------------------------------------------------------
__global__ __launch_bounds__(256) void dw_kernel(
    const float* __restrict__ x,
    const float* __restrict__ dw_w, const float* __restrict__ dw_b,
    const float* __restrict__ g1, const float* __restrict__ b1,
    const float* __restrict__ m1, const float* __restrict__ v1,
    const float* __restrict__ pw_w, const float* __restrict__ pw_b,
    const float* __restrict__ g2, const float* __restrict__ b2,
    const float* __restrict__ m2, const float* __restrict__ v2)
{
    __shared__ float xs[XPAD_TOP + HW + XPAD_BOT + 3];
    __shared__ float red[8];
    __shared__ int s_keep;

    const int bc = blockIdx.x;
    const int c  = bc & (C_IN - 1);
    const int t  = threadIdx.x;
    const float* xp = x + (size_t)bc * HW;

    if (bc < 128) {
        int id = bc * 256 + t;
        int co = id >> 7;
        float s2 = g2[co] * rsqrtf(v2[co] + BN_EPS);
        g_w2[id] = __float2half(pw_w[id] * s2);
        if (id < C_OUT) {
            float s2b = g2[id] * rsqrtf(v2[id] + BN_EPS);
            g_bias2[id] = pw_b[id] * s2b + b2[id] - m2[id] * s2b;
        }
        if (id < BATCH * C_OUT) g_max[id] = 0u;
        if (id == 0) g_unit = NPW;
    }

    if (t < XPAD_TOP + XPAD_BOT) {
        int idx = (t < XPAD_TOP) ? t : (XPAD_TOP + HW + (t - XPAD_TOP));
        xs[idx] = 0.f;
    }
    {
        const float4* src = (const float4*)xp;
        float4* dst = (float4*)(xs + XPAD_TOP);
        #pragma unroll
        for (int k = 0; k < 4; k++) {
            int id = t + k * 256;
            if (id < HW / 4) dst[id] = __ldcs(src + id);
        }
    }

    float s1   = g1[c] * rsqrtf(v1[c] + BN_EPS);
    float bias = dw_b[c] * s1 + b1[c] - m1[c] * s1;
    float w00 = dw_w[c*9+0]*s1, w01 = dw_w[c*9+1]*s1, w02 = dw_w[c*9+2]*s1;
    float w10 = dw_w[c*9+3]*s1, w11 = dw_w[c*9+4]*s1, w12 = dw_w[c*9+5]*s1;
    float w20 = dw_w[c*9+6]*s1, w21 = dw_w[c*9+7]*s1, w22 = dw_w[c*9+8]*s1;

    __syncthreads();

    const int row = t >> 2;
    const int cb  = (t & 3) * 14;
    const bool act = (t < 224);

    float vals[14];
    float mx = 0.f;
    if (act) {
        const float* bp = xs + XPAD_TOP + (row - 1) * WID + cb - 1;
        float top[16], mid[16], bot[16];
        #pragma unroll
        for (int j = 0; j < 16; j++) {
            top[j] = bp[j];
            mid[j] = bp[WID + j];
            bot[j] = bp[2 * WID + j];
        }
        if (cb == 0)  { top[0]  = 0.f; mid[0]  = 0.f; bot[0]  = 0.f; }
        if (cb == 42) { top[15] = 0.f; mid[15] = 0.f; bot[15] = 0.f; }
        #pragma unroll
        for (int j = 0; j < 14; j++) {
            float acc = top[j] * w00;
            acc += top[j+1] * w01;
            acc += top[j+2] * w02;
            acc += mid[j] * w10;
            acc += mid[j+1] * w11;
            acc += mid[j+2] * w12;
            acc += bot[j] * w20;
            acc += bot[j+1] * w21;
            acc += bot[j+2] * w22;
            float v = fmaxf(acc + bias, 0.f);
            vals[j] = v;
            mx = fmaxf(mx, v);
        }
    }

    #pragma unroll
    for (int off = 16; off > 0; off >>= 1)
        mx = fmaxf(mx, __shfl_xor_sync(0xffffffffu, mx, off));
    if ((t & 31) == 0) red[t >> 5] = mx;
    __syncthreads();
    if (t == 0) {
        float m = red[0];
        #pragma unroll
        for (int i = 1; i < 7; i++) m = fmaxf(m, red[i]);
        int k = (m >= DW_THRESH) ? 1 : 0;
        s_keep = k;
        g_keep[bc] = (unsigned char)k;
    }
    __syncthreads();

    if (s_keep && act) {
        __half2* yp = (__half2*)(g_y + (size_t)bc * HW + row * WID + cb);
        #pragma unroll
        for (int j = 0; j < 7; j++)
            yp[j] = __floats2half2_rn(vals[2*j], vals[2*j+1]);
    }
}

// ---------------------------------------------------------------------------
// K2: persistent pointwise GEMM, dynamic work-stealing.
//     Seed unit = blockIdx.x; next units via atomicAdd ticket (balance ±1 unit).
//     A reloaded only when coblk changes (monotonic -> at most once per CTA).
//     B double-buffered; next unit's fill overlaps current mma+epilogue.
// ---------------------------------------------------------------------------
__device__ __forceinline__ void fill_A(uint32_t as_addr, int coblk, int t) {
    const char* asrc = (const char*)(g_w2 + (size_t)coblk * MC * C_IN);
    #pragma unroll
    for (int i = 0; i < 8; i++) {
        int id = i * 256 + t;
        int co = id >> 4;
        int kq = id & 15;
        cp_async16(as_addr + (co * SSTR + kq * 8) * 2, asrc + id * 16, 16);
    }
}
__device__ __forceinline__ void fill_B(uint32_t bs_addr, int b, int tile, int t) {
    const __half* yb = g_y + (size_t)b * C_IN * HW;
    const unsigned char* keep = g_keep + b * C_IN;
    int pix0 = tile * NC;
    #pragma unroll
    for (int i = 0; i < 8; i++) {
        int id = i * 256 + t;
        int k  = id >> 4;
        int pq = id & 15;
        int pix = pix0 + pq * 8;
        int sz = (pix < HW && keep[k]) ? 16 : 0;
        cp_async16(bs_addr + (k * SSTR + pq * 8) * 2, yb + (size_t)k * HW + pix, sz);
    }
}

__global__ __launch_bounds__(256, 2) void pw_kernel(float* __restrict__ out)
{
    extern __shared__ __half smem[];
    __half* As = smem;                        // [128 co][SSTR]
    __shared__ int s_next[2];

    const int t    = threadIdx.x;
    const int lane = t & 31;
    const int w    = t >> 5;
    const int g    = lane >> 2;
    const int tg   = lane & 3;
    const int wm   = w >> 1;
    const int wn   = w & 1;

    uint32_t as_addr = (uint32_t)__cvta_generic_to_shared(As);
    uint32_t bs_addr[2] = {
        (uint32_t)__cvta_generic_to_shared(smem + AS_HALFS),
        (uint32_t)__cvta_generic_to_shared(smem + 2 * AS_HALFS)
    };

    // seed unit + first ticket
    int u = blockIdx.x;                       // < NPW <= NUNITS
    int coblk = u / 800, rr = u % 800, b = rr / 25, tile = rr % 25;
    if (t == 0) s_next[0] = atomicAdd(&g_unit, 1);
    fill_A(as_addr, coblk, t);
    fill_B(bs_addr[0], b, tile, t);
    cp_async_commit();
    int cur = 0;

    uint32_t a_off = (((wm * 32 + (lane & 15)) * SSTR + (lane >> 4) * 8) << 1);
    uint32_t b_off = ((((lane & 15)) * SSTR + wn * 64 + (lane >> 4) * 8) << 1);

    for (int it = 0; ; it++) {
        __syncthreads();                      // s_next[it&1] visible
        const int un = s_next[it & 1];
        const bool have = (un < NUNITS);
        int ncoblk = 0, nb = 0, ntile = 0;
        bool pref = false;
        if (have) {
            ncoblk = un / 800; int r2 = un % 800; nb = r2 / 25; ntile = r2 % 25;
            pref = (ncoblk == coblk);
            if (pref) {
                fill_B(bs_addr[cur ^ 1], nb, ntile, t);
                cp_async_commit();
            }
            if (t == 0) s_next[(it + 1) & 1] = atomicAdd(&g_unit, 1);
        }
        if (pref) cp_async_wait<1>(); else cp_async_wait<0>();
        __syncthreads();

        // ---- mma over As x Bs[cur] ----
        float c[2][8][4];
        #pragma unroll
        for (int mt = 0; mt < 2; mt++)
            #pragma unroll
            for (int nt = 0; nt < 8; nt++)
                #pragma unroll
                for (int i = 0; i < 4; i++) c[mt][nt][i] = 0.f;

        uint32_t a_base = as_addr + a_off;
        uint32_t b_base = bs_addr[cur] + b_off;
        #pragma unroll
        for (int ks = 0; ks < 8; ks++) {
            uint32_t a[2][4], bb[4][4];
            #pragma unroll
            for (int mt = 0; mt < 2; mt++)
                ldsm_x4(a[mt], a_base + mt * (16 * SSTR * 2) + ks * 32);
            #pragma unroll
            for (int ntp = 0; ntp < 4; ntp++)
                ldsm_x4_t(bb[ntp], b_base + ntp * 32 + ks * (16 * SSTR * 2));
            #pragma unroll
            for (int mt = 0; mt < 2; mt++) {
                #pragma unroll
                for (int ntp = 0; ntp < 4; ntp++) {
                    mma_f16(c[mt][ntp * 2 + 0], a[mt], &bb[ntp][0]);
                    mma_f16(c[mt][ntp * 2 + 1], a[mt], &bb[ntp][2]);
                }
            }
        }

        // ---- epilogue: bias + relu + quad-max -> global REDG.MAX + stores ----
        const int co0  = coblk * MC;
        const int pix0 = tile * NC;
        float* outb = out + ((size_t)b * C_OUT + co0) * HW;
        unsigned int* gmx = g_max + b * C_OUT + co0;
        #pragma unroll
        for (int mt = 0; mt < 2; mt++) {
            #pragma unroll
            for (int half = 0; half < 2; half++) {
                int co_l = wm * 32 + mt * 16 + half * 8 + g;
                float bs = g_bias2[co0 + co_l];
                float mxv = 0.f;
                float* orow = outb + (size_t)co_l * HW;
                #pragma unroll
                for (int nt = 0; nt < 8; nt++) {
                    float v0 = fmaxf(c[mt][nt][half * 2 + 0] + bs, 0.f);
                    float v1 = fmaxf(c[mt][nt][half * 2 + 1] + bs, 0.f);
                    int pix = pix0 + wn * 64 + nt * 8 + tg * 2;
                    if (pix < HW) {
                        mxv = fmaxf(mxv, fmaxf(v0, v1));
                        __stcs((float2*)(orow + pix), make_float2(v0, v1));
                    }
                }
                mxv = fmaxf(mxv, __shfl_xor_sync(0xffffffffu, mxv, 1));
                mxv = fmaxf(mxv, __shfl_xor_sync(0xffffffffu, mxv, 2));
                if (tg == 0) atomicMax(&gmx[co_l], __float_as_uint(mxv));
            }
        }
        __syncthreads();                      // all reads of Bs[cur]/As done
        if (!have) break;
        if (!pref) {                          // coblk boundary: reload A (+B)
            fill_A(as_addr, ncoblk, t);
            fill_B(bs_addr[cur ^ 1], nb, ntile, t);
            cp_async_commit();
        }
        coblk = ncoblk; b = nb; tile = ntile;
        cur ^= 1;
    }
}

// ---------------------------------------------------------------------------
// K3: second cut — 256 blocks, each owns 32 (b,co) maps
// ---------------------------------------------------------------------------
__global__ __launch_bounds__(256) void cut_kernel(float* __restrict__ out)
{
    const int base = blockIdx.x * 32;
    for (int m = 0; m < 32; m++) {
        int bc = base + m;
        if (__uint_as_float(g_max[bc]) >= PW_THRESH) continue;
        float4* p = (float4*)(out + (size_t)bc * HW);
        for (int i = threadIdx.x; i < HW / 4; i += blockDim.x)
            p[i] = make_float4(0.f, 0.f, 0.f, 0.f);
    }
}

// ---------------------------------------------------------------------------
extern "C" void kernel_launch(void* const* d_in, const int* in_sizes, int n_in,
                              void* d_out, int out_size)
{
    const float* x     = (const float*)d_in[0];
    const float* dw_w  = (const float*)d_in[1];
    const float* dw_b  = (const float*)d_in[2];
    const float* bn1_g = (const float*)d_in[3];
    const float* bn1_b = (const float*)d_in[4];
    const float* bn1_m = (const float*)d_in[5];
    const float* bn1_v = (const float*)d_in[6];
    const float* pw_w  = (const float*)d_in[7];
    const float* pw_b  = (const float*)d_in[8];
    const float* bn2_g = (const float*)d_in[9];
    const float* bn2_b = (const float*)d_in[10];
    const float* bn2_m = (const float*)d_in[11];
    const float* bn2_v = (const float*)d_in[12];
    float* out = (float*)d_out;

    static bool attrs_set = false;
    if (!attrs_set) {
        cudaFuncSetAttribute(pw_kernel, cudaFuncAttributeMaxDynamicSharedMemorySize, PW_SMEM_BYTES);
        attrs_set = true;
    }

    dw_kernel<<<BATCH * C_IN, 256>>>(x, dw_w, dw_b, bn1_g, bn1_b, bn1_m, bn1_v,
                                     pw_w, pw_b, bn2_g, bn2_b, bn2_m, bn2_v);
    pw_kernel<<<NPW, 256, PW_SMEM_BYTES>>>(out);
    cut_kernel<<<256, 256>>>(out);
}

// round 17
// speedup vs baseline: 1.0362x; 1.0362x over previous
#include <cuda_runtime.h>
#include <cuda_fp16.h>
#include <cstdint>

#define BATCH 32
#define C_IN 128
#define C_OUT 256
#define HGT 56
#define WID 56
#define HW 3136
#define BN_EPS 1e-5f
#define DW_THRESH 4.0f
#define PW_THRESH 0.001f

#define NTILES 25               // ceil(3136/128) pixel tiles
#define MC 128                  // co per CTA tile
#define NC 128                  // pixels per CTA tile
#define SSTR 136                // smem row stride in halfs (128 + 8 pad)
#define AS_HALFS (MC * SSTR)    // 17408 halfs = 34816 B
#define NUNITS 1600             // 2 co-blocks * 32 batch * 25 tiles
#define NPW 296                 // persistent CTAs (2 per SM * 148)
#define PW_SMEM_BYTES (3 * AS_HALFS * 2 + 512)   // A + 2xB + smax

#define XPAD_TOP 56             // dw smem top pad (zeroed)
#define XPAD_BOT 57             // dw smem bottom pad (zeroed)

// ---------------- device scratch ----------------
__device__ __half g_y[BATCH * C_IN * HW];       // post-dw activations [b][ci][pix]
__device__ __half g_w2[C_OUT * C_IN];           // BN2-folded weights [co][ci]
__device__ float g_bias2[C_OUT];
__device__ unsigned int g_max[BATCH * C_OUT];
__device__ unsigned char g_keep[BATCH * C_IN];  // cut-1 survival flag

__device__ __forceinline__ void ldsm_x4(uint32_t* r, uint32_t addr) {
    asm volatile("ldmatrix.sync.aligned.m8n8.x4.shared.b16 {%0,%1,%2,%3}, [%4];"
                 : "=r"(r[0]), "=r"(r[1]), "=r"(r[2]), "=r"(r[3]) : "r"(addr));
}
__device__ __forceinline__ void ldsm_x4_t(uint32_t* r, uint32_t addr) {
    asm volatile("ldmatrix.sync.aligned.m8n8.x4.trans.shared.b16 {%0,%1,%2,%3}, [%4];"
                 : "=r"(r[0]), "=r"(r[1]), "=r"(r[2]), "=r"(r[3]) : "r"(addr));
}
__device__ __forceinline__ void mma_f16(float* c, const uint32_t* a, const uint32_t* b) {
    asm volatile(
        "mma.sync.aligned.m16n8k16.row.col.f32.f16.f16.f32 "
        "{%0,%1,%2,%3}, {%4,%5,%6,%7}, {%8,%9}, {%0,%1,%2,%3};"
        : "+f"(c[0]), "+f"(c[1]), "+f"(c[2]), "+f"(c[3])
        : "r"(a[0]), "r"(a[1]), "r"(a[2]), "r"(a[3]), "r"(b[0]), "r"(b[1]));
}
__device__ __forceinline__ void cp_async16(uint32_t dst, const void* src, int src_size) {
    asm volatile("cp.async.cg.shared.global [%0], [%1], 16, %2;"
                 :: "r"(dst), "l"(src), "r"(src_size) : "memory");
}
__device__ __forceinline__ void cp_async_commit() {
    asm volatile("cp.async.commit_group;" ::: "memory");
}
template <int N>
__device__ __forceinline__ void cp_async_wait() {
    asm volatile("cp.async.wait_group %0;" :: "n"(N) : "memory");
}

// ---------------------------------------------------------------------------
// K1: depthwise 3x3 + bias + BN1 + ReLU + cut(4.0), one block per (b,c) map.
//     cp.async x staging; zero-padded 1D smem; register-halo convolution.
//     Blocks 0..127 additionally fold BN2 into pw weights (prep).
// ---------------------------------------------------------------------------
__global__ __launch_bounds__(256) void dw_kernel(
    const float* __restrict__ x,
    const float* __restrict__ dw_w, const float* __restrict__ dw_b,
    const float* __restrict__ g1, const float* __restrict__ b1,
    const float* __restrict__ m1, const float* __restrict__ v1,
    const float* __restrict__ pw_w, const float* __restrict__ pw_b,
    const float* __restrict__ g2, const float* __restrict__ b2,
    const float* __restrict__ m2, const float* __restrict__ v2)
{
    __shared__ float xs[XPAD_TOP + HW + XPAD_BOT + 3];
    __shared__ float red[8];
    __shared__ int s_keep;

    const int bc = blockIdx.x;
    const int c  = bc & (C_IN - 1);
    const int t  = threadIdx.x;
    const float* xp = x + (size_t)bc * HW;

    // async stage of the whole map (784 x 16B), overlaps prep + weight math
    {
        uint32_t dst = (uint32_t)__cvta_generic_to_shared(xs + XPAD_TOP);
        #pragma unroll
        for (int k = 0; k < 4; k++) {
            int id = t + k * 256;
            if (id < HW / 4)
                cp_async16(dst + id * 16, xp + id * 4, 16);
        }
        cp_async_commit();
    }

    // ---- folded prep work (blocks 0..127 cover 32768 weights) ----
    if (bc < 128) {
        int id = bc * 256 + t;
        int co = id >> 7;
        float s2 = g2[co] * rsqrtf(v2[co] + BN_EPS);
        g_w2[id] = __float2half(pw_w[id] * s2);
        if (id < C_OUT) {
            float s2b = g2[id] * rsqrtf(v2[id] + BN_EPS);
            g_bias2[id] = pw_b[id] * s2b + b2[id] - m2[id] * s2b;
        }
        if (id < BATCH * C_OUT) g_max[id] = 0u;
    }

    // zero pads (113 cells)
    if (t < XPAD_TOP + XPAD_BOT) {
        int idx = (t < XPAD_TOP) ? t : (XPAD_TOP + HW + (t - XPAD_TOP));
        xs[idx] = 0.f;
    }

    float s1   = g1[c] * rsqrtf(v1[c] + BN_EPS);
    float bias = dw_b[c] * s1 + b1[c] - m1[c] * s1;
    float w00 = dw_w[c*9+0]*s1, w01 = dw_w[c*9+1]*s1, w02 = dw_w[c*9+2]*s1;
    float w10 = dw_w[c*9+3]*s1, w11 = dw_w[c*9+4]*s1, w12 = dw_w[c*9+5]*s1;
    float w20 = dw_w[c*9+6]*s1, w21 = dw_w[c*9+7]*s1, w22 = dw_w[c*9+8]*s1;

    cp_async_wait<0>();
    __syncthreads();

    const int row = t >> 2;               // 0..55 (t<224)
    const int cb  = (t & 3) * 14;         // 0,14,28,42
    const bool act = (t < 224);

    float vals[14];
    float mx = 0.f;
    if (act) {
        const float* bp = xs + XPAD_TOP + (row - 1) * WID + cb - 1;
        float top[16], mid[16], bot[16];
        #pragma unroll
        for (int j = 0; j < 16; j++) {
            top[j] = bp[j];
            mid[j] = bp[WID + j];
            bot[j] = bp[2 * WID + j];
        }
        if (cb == 0)  { top[0]  = 0.f; mid[0]  = 0.f; bot[0]  = 0.f; }
        if (cb == 42) { top[15] = 0.f; mid[15] = 0.f; bot[15] = 0.f; }
        #pragma unroll
        for (int j = 0; j < 14; j++) {
            float acc = top[j] * w00;
            acc += top[j+1] * w01;
            acc += top[j+2] * w02;
            acc += mid[j] * w10;
            acc += mid[j+1] * w11;
            acc += mid[j+2] * w12;
            acc += bot[j] * w20;
            acc += bot[j+1] * w21;
            acc += bot[j+2] * w22;
            float v = fmaxf(acc + bias, 0.f);
            vals[j] = v;
            mx = fmaxf(mx, v);
        }
    }

    #pragma unroll
    for (int off = 16; off > 0; off >>= 1)
        mx = fmaxf(mx, __shfl_xor_sync(0xffffffffu, mx, off));
    if ((t & 31) == 0) red[t >> 5] = mx;
    __syncthreads();
    if (t == 0) {
        float m = red[0];
        #pragma unroll
        for (int i = 1; i < 7; i++) m = fmaxf(m, red[i]);
        int k = (m >= DW_THRESH) ? 1 : 0;
        s_keep = k;
        g_keep[bc] = (unsigned char)k;
    }
    __syncthreads();

    if (s_keep && act) {
        __half2* yp = (__half2*)(g_y + (size_t)bc * HW + row * WID + cb);
        #pragma unroll
        for (int j = 0; j < 7; j++)
            yp[j] = __floats2half2_rn(vals[2*j], vals[2*j+1]);
    }
}

// ---------------------------------------------------------------------------
// K2: persistent pointwise GEMM via mma.sync fp16 (R14 base).
//     Static chunks of the 1600 (coblk,b,tile) units; A loaded per coblk run;
//     B double-buffered with RELAXED prefetch (A validity only needs coblk).
// ---------------------------------------------------------------------------
__device__ __forceinline__ void fill_A(uint32_t as_addr, int coblk, int t) {
    const char* asrc = (const char*)(g_w2 + (size_t)coblk * MC * C_IN);
    #pragma unroll
    for (int i = 0; i < 8; i++) {
        int id = i * 256 + t;
        int co = id >> 4;
        int kq = id & 15;
        cp_async16(as_addr + (co * SSTR + kq * 8) * 2, asrc + id * 16, 16);
    }
}
__device__ __forceinline__ void fill_B(uint32_t bs_addr, int b, int tile, int t) {
    const __half* yb = g_y + (size_t)b * C_IN * HW;
    const unsigned char* keep = g_keep + b * C_IN;
    int pix0 = tile * NC;
    #pragma unroll
    for (int i = 0; i < 8; i++) {
        int id = i * 256 + t;
        int k  = id >> 4;
        int pq = id & 15;
        int pix = pix0 + pq * 8;
        int sz = (pix < HW && keep[k]) ? 16 : 0;
        cp_async16(bs_addr + (k * SSTR + pq * 8) * 2, yb + (size_t)k * HW + pix, sz);
    }
}

__global__ __launch_bounds__(256, 2) void pw_kernel(float* __restrict__ out)
{
    extern __shared__ __half smem[];
    __half* As = smem;                        // [128 co][SSTR]
    unsigned int* smax = (unsigned int*)(smem + 3 * AS_HALFS);  // [128]

    const int cta  = blockIdx.x;
    const int t    = threadIdx.x;
    const int lane = t & 31;
    const int w    = t >> 5;
    const int g    = lane >> 2;
    const int tg   = lane & 3;
    const int wm   = w >> 1;
    const int wn   = w & 1;

    const int u0 = cta * NUNITS / NPW;
    const int u1 = (cta + 1) * NUNITS / NPW;
    if (u0 >= u1) return;

    uint32_t as_addr = (uint32_t)__cvta_generic_to_shared(As);
    uint32_t bs_addr[2] = {
        (uint32_t)__cvta_generic_to_shared(smem + AS_HALFS),
        (uint32_t)__cvta_generic_to_shared(smem + 2 * AS_HALFS)
    };

    if (t < MC) smax[t] = 0u;

    // unit u -> coblk = u/800, b = (u%800)/25, tile = u%25
    int coblk = u0 / 800, rr = u0 % 800, b = rr / 25, tile = rr % 25;
    fill_A(as_addr, coblk, t);
    fill_B(bs_addr[0], b, tile, t);
    cp_async_commit();
    int cur = 0;

    uint32_t a_off = (((wm * 32 + (lane & 15)) * SSTR + (lane >> 4) * 8) << 1);
    uint32_t b_off = ((((lane & 15)) * SSTR + wn * 64 + (lane >> 4) * 8) << 1);

    for (int u = u0; u < u1; u++) {
        // decode next unit; prefetch its B whenever A (coblk) stays valid
        int ncoblk = 0, nb = 0, ntile = 0;
        bool have_next = (u + 1 < u1);
        bool pref = false;
        if (have_next) {
            int un = u + 1;
            ncoblk = un / 800; int r2 = un % 800; nb = r2 / 25; ntile = r2 % 25;
            pref = (ncoblk == coblk);          // RELAXED: b may change freely
            if (pref) {
                fill_B(bs_addr[cur ^ 1], nb, ntile, t);
                cp_async_commit();
            }
        }
        if (pref) cp_async_wait<1>(); else cp_async_wait<0>();
        __syncthreads();

        // ---- mma over As x Bs[cur] ----
        float c[2][8][4];
        #pragma unroll
        for (int mt = 0; mt < 2; mt++)
            #pragma unroll
            for (int nt = 0; nt < 8; nt++)
                #pragma unroll
                for (int i = 0; i < 4; i++) c[mt][nt][i] = 0.f;

        uint32_t a_base = as_addr + a_off;
        uint32_t b_base = bs_addr[cur] + b_off;
        #pragma unroll
        for (int ks = 0; ks < 8; ks++) {
            uint32_t a[2][4], bb[4][4];
            #pragma unroll
            for (int mt = 0; mt < 2; mt++)
                ldsm_x4(a[mt], a_base + mt * (16 * SSTR * 2) + ks * 32);
            #pragma unroll
            for (int ntp = 0; ntp < 4; ntp++)
                ldsm_x4_t(bb[ntp], b_base + ntp * 32 + ks * (16 * SSTR * 2));
            #pragma unroll
            for (int mt = 0; mt < 2; mt++) {
                #pragma unroll
                for (int ntp = 0; ntp < 4; ntp++) {
                    mma_f16(c[mt][ntp * 2 + 0], a[mt], &bb[ntp][0]);
                    mma_f16(c[mt][ntp * 2 + 1], a[mt], &bb[ntp][2]);
                }
            }
        }

        // ---- epilogue: bias + relu + per-co max + streaming stores ----
        const int co0  = coblk * MC;
        const int pix0 = tile * NC;
        float* outb = out + ((size_t)b * C_OUT + co0) * HW;
        #pragma unroll
        for (int mt = 0; mt < 2; mt++) {
            #pragma unroll
            for (int half = 0; half < 2; half++) {
                int co_l = wm * 32 + mt * 16 + half * 8 + g;
                float bs = g_bias2[co0 + co_l];
                float mxv = 0.f;
                float* orow = outb + (size_t)co_l * HW;
                #pragma unroll
                for (int nt = 0; nt < 8; nt++) {
                    float v0 = fmaxf(c[mt][nt][half * 2 + 0] + bs, 0.f);
                    float v1 = fmaxf(c[mt][nt][half * 2 + 1] + bs, 0.f);
                    int pix = pix0 + wn * 64 + nt * 8 + tg * 2;
                    if (pix < HW) {
                        mxv = fmaxf(mxv, fmaxf(v0, v1));
                        __stcs((float2*)(orow + pix), make_float2(v0, v1));
                    }
                }
                mxv = fmaxf(mxv, __shfl_xor_sync(0xffffffffu, mxv, 1));
                mxv = fmaxf(mxv, __shfl_xor_sync(0xffffffffu, mxv, 2));
                if (tg == 0) atomicMax(&smax[co_l], __float_as_uint(mxv));
            }
        }
        __syncthreads();                       // all reads of Bs[cur]/As + smax done
        if (t < MC) {
            atomicMax(&g_max[b * C_OUT + co0 + t], smax[t]);
            smax[t] = 0u;
        }
        if (have_next && !pref) {              // coblk boundary (rare): reload A (+B)
            fill_A(as_addr, ncoblk, t);
            fill_B(bs_addr[cur ^ 1], nb, ntile, t);
            cp_async_commit();
        }
        coblk = ncoblk; b = nb; tile = ntile;
        cur ^= 1;
    }
}

// ---------------------------------------------------------------------------
// K3: second cut — 256 blocks, each owns 32 (b,co) maps
// ---------------------------------------------------------------------------
__global__ __launch_bounds__(256) void cut_kernel(float* __restrict__ out)
{
    const int base = blockIdx.x * 32;
    for (int m = 0; m < 32; m++) {
        int bc = base + m;
        if (__uint_as_float(g_max[bc]) >= PW_THRESH) continue;
        float4* p = (float4*)(out + (size_t)bc * HW);
        for (int i = threadIdx.x; i < HW / 4; i += blockDim.x)
            p[i] = make_float4(0.f, 0.f, 0.f, 0.f);
    }
}

// ---------------------------------------------------------------------------
extern "C" void kernel_launch(void* const* d_in, const int* in_sizes, int n_in,
                              void* d_out, int out_size)
{
    const float* x     = (const float*)d_in[0];
    const float* dw_w  = (const float*)d_in[1];
    const float* dw_b  = (const float*)d_in[2];
    const float* bn1_g = (const float*)d_in[3];
    const float* bn1_b = (const float*)d_in[4];
    const float* bn1_m = (const float*)d_in[5];
    const float* bn1_v = (const float*)d_in[6];
    const float* pw_w  = (const float*)d_in[7];
    const float* pw_b  = (const float*)d_in[8];
    const float* bn2_g = (const float*)d_in[9];
    const float* bn2_b = (const float*)d_in[10];
    const float* bn2_m = (const float*)d_in[11];
    const float* bn2_v = (const float*)d_in[12];
    float* out = (float*)d_out;

    static bool attrs_set = false;
    if (!attrs_set) {
        cudaFuncSetAttribute(pw_kernel, cudaFuncAttributeMaxDynamicSharedMemorySize, PW_SMEM_BYTES);
        attrs_set = true;
    }

    dw_kernel<<<BATCH * C_IN, 256>>>(x, dw_w, dw_b, bn1_g, bn1_b, bn1_m, bn1_v,
                                     pw_w, pw_b, bn2_g, bn2_b, bn2_m, bn2_v);
    pw_kernel<<<NPW, 256, PW_SMEM_BYTES>>>(out);
    cut_kernel<<<256, 256>>>(out);
}